// round 16
// baseline (speedup 1.0000x reference)
#include <cuda_runtime.h>
#include <cuda_fp16.h>
#include <cstdint>

// Problem dims
#define BB 4
#define SS 4096
#define DD 256
#define CC 8921
#define CP 8960   // C padded to multiple of 128
#define KC 64     // K-chunk (halves)
#define P72 72    // smem pitch in halves; 144B rows -> LDSM conflict-free

// ---------------- device scratch (zero-initialized at module load) ----------
__device__ __align__(256) __half g_xh[BB * SS * DD];            // x fp16 [b][s][d]
__device__ __align__(256) __half g_xT[BB * DD * SS];            // x^T fp16 [b][d][s]
__device__ __align__(256) __half g_Wh[CP * DD];                 // W fp16 (pad rows stay 0)
__device__ __align__(256) __half g_e [(size_t)BB * CP * SS];    // exp(scores) fp16
__device__ __align__(256) float  g_Zp[(size_t)BB * CP * 128];   // per-(row, stile*4+warp) partials
__device__ __align__(256) float  g_Z [BB * CP];                 // row sums

// ---------------- helpers ---------------------------------------------------
__device__ __forceinline__ float fast_exp(float x) {
    float y = x * 1.4426950408889634f;
    y = fminf(fmaxf(y, -80.0f), 80.0f);
    float n = rintf(y);
    float f = y - n;
    float p = 1.3333558146e-3f;
    p = fmaf(p, f, 9.6181291076e-3f);
    p = fmaf(p, f, 5.5504108664e-2f);
    p = fmaf(p, f, 2.4022650696e-1f);
    p = fmaf(p, f, 6.9314718056e-1f);
    p = fmaf(p, f, 1.0f);
    return p * __int_as_float((__float2int_rn(n) + 127) << 23);
}

#define MMA16816(d, a, b)                                                     \
    asm volatile(                                                             \
        "mma.sync.aligned.m16n8k16.row.col.f32.f16.f16.f32 "                  \
        "{%0,%1,%2,%3}, {%4,%5,%6,%7}, {%8,%9}, {%0,%1,%2,%3};\n"             \
        : "+f"((d)[0]), "+f"((d)[1]), "+f"((d)[2]), "+f"((d)[3])              \
        : "r"((a)[0]), "r"((a)[1]), "r"((a)[2]), "r"((a)[3]),                 \
          "r"((b)[0]), "r"((b)[1]))

__device__ __forceinline__ void ldsm4(uint32_t* r, const __half* p) {
    uint32_t a = (uint32_t)__cvta_generic_to_shared(p);
    asm volatile("ldmatrix.sync.aligned.m8n8.x4.shared.b16 {%0,%1,%2,%3}, [%4];\n"
                 : "=r"(r[0]), "=r"(r[1]), "=r"(r[2]), "=r"(r[3]) : "r"(a));
}

__device__ __forceinline__ void cpa16(const __half* smem_dst, const __half* gmem_src) {
    uint32_t d = (uint32_t)__cvta_generic_to_shared(smem_dst);
    asm volatile("cp.async.cg.shared.global [%0], [%1], 16;\n" :: "r"(d), "l"(gmem_src));
}
#define CP_COMMIT() asm volatile("cp.async.commit_group;\n")
#define CP_WAIT0()  asm volatile("cp.async.wait_group 0;\n")

// ---------------- K0: fused conversions (x -> fp16 + x^T; W -> fp16) --------
__global__ __launch_bounds__(256) void k_conv(const float* __restrict__ x,
                                              const float* __restrict__ W) {
    const int tid = threadIdx.x;
    if (blockIdx.z == BB) {
        int bid = blockIdx.y * 2 + blockIdx.x;           // 0..255
        int i0 = bid * 256 + tid;
        const int n4 = CC * DD / 4;
        for (int i = i0; i < n4; i += 256 * 256) {
            float4 v = *(const float4*)(W + (size_t)i * 4);
            __half2 h0 = __floats2half2_rn(v.x, v.y);
            __half2 h1 = __floats2half2_rn(v.z, v.w);
            *(__half2*)(g_Wh + (size_t)i * 4)     = h0;
            *(__half2*)(g_Wh + (size_t)i * 4 + 2) = h1;
        }
        return;
    }
    __shared__ float t[32][132];
    const int d0 = blockIdx.x * 128, s0 = blockIdx.y * 32, b = blockIdx.z;
#pragma unroll
    for (int r = 0; r < 4; r++) {
        int slot = r * 256 + tid;
        int s = slot >> 5;
        int d = (slot & 31) * 4;
        float4 v = *(const float4*)(x + ((size_t)b * SS + s0 + s) * DD + d0 + d);
        __half2 h0 = __floats2half2_rn(v.x, v.y);
        __half2 h1 = __floats2half2_rn(v.z, v.w);
        *(__half2*)(g_xh + ((size_t)b * SS + s0 + s) * DD + d0 + d)     = h0;
        *(__half2*)(g_xh + ((size_t)b * SS + s0 + s) * DD + d0 + d + 2) = h1;
        *(float4*)&t[s][d] = v;
    }
    __syncthreads();
#pragma unroll
    for (int r = 0; r < 8; r++) {
        int slot = r * 256 + tid;
        int d = slot >> 4;
        int sp = slot & 15;
        __half2 h = __floats2half2_rn(t[2 * sp][d], t[2 * sp + 1][d]);
        *(__half2*)(g_xT + ((size_t)b * DD + d0 + d) * SS + s0 + 2 * sp) = h;
    }
}

// ---------------- K1: scores GEMM + exp + deterministic partial row sums ----
// CTA 128(c) x 128(s), 256 threads. K=D=256 in 4 chunks of 64 halves,
// 2-stage double buffer. Stage: rows 0..127 = A (W), rows 128..255 = B (x).
__global__ __launch_bounds__(256) void k_scores() {
    extern __shared__ __half sm1[];
#define S1(st_, r_, c_) sm1[(((st_) * 256) + (r_)) * P72 + (c_)]

    const int tid = threadIdx.x;
    const int wid = tid >> 5, lane = tid & 31;
    const int g = lane >> 2, tg = lane & 3;
    const int warp_m = wid >> 2, warp_n = wid & 3;

    const int c0 = blockIdx.x * 128;
    const int s0 = blockIdx.y * 128;
    const int b  = blockIdx.z;

    const __half* Wt = g_Wh + (size_t)c0 * DD;
    const __half* Xt = g_xh + ((size_t)b * SS + s0) * DD;

    float acc[4][4][4];
#pragma unroll
    for (int i = 0; i < 4; i++)
#pragma unroll
        for (int j = 0; j < 4; j++)
#pragma unroll
            for (int k = 0; k < 4; k++) acc[i][j][k] = 0.0f;

    const int lr = tid >> 3, c16 = tid & 7;   // loader row 0..31, 16B col 0..7

    const int a_r = lane & 15, a_c = (lane >> 4) << 3;
    const int b_r = ((lane >> 4) << 3) + (lane & 7);
    const int b_c = ((lane >> 3) & 1) << 3;

    // prologue: stage 0 (kc = 0)
#pragma unroll
    for (int i = 0; i < 4; i++) {
        int r = lr + 32 * i;
        cpa16(&S1(0, r, c16 * 8),       Wt + (size_t)r * DD + c16 * 8);
        cpa16(&S1(0, 128 + r, c16 * 8), Xt + (size_t)r * DD + c16 * 8);
    }
    CP_COMMIT();

#pragma unroll 1
    for (int ch = 0; ch < DD / KC; ch++) {
        const int buf = ch & 1;
        CP_WAIT0();
        __syncthreads();
        if (ch + 1 < DD / KC) {
            const int nb = buf ^ 1;
            const int kc = (ch + 1) * KC;
#pragma unroll
            for (int i = 0; i < 4; i++) {
                int r = lr + 32 * i;
                cpa16(&S1(nb, r, c16 * 8),       Wt + (size_t)r * DD + kc + c16 * 8);
                cpa16(&S1(nb, 128 + r, c16 * 8), Xt + (size_t)r * DD + kc + c16 * 8);
            }
            CP_COMMIT();
        }
#pragma unroll
        for (int kk = 0; kk < KC; kk += 16) {
            uint32_t af[4][4], bf[4][2];
#pragma unroll
            for (int fm = 0; fm < 4; fm++)
                ldsm4(af[fm], &S1(buf, warp_m * 64 + fm * 16 + a_r, kk + a_c));
#pragma unroll
            for (int fp = 0; fp < 2; fp++) {
                uint32_t t4[4];
                ldsm4(t4, &S1(buf, 128 + warp_n * 32 + fp * 16 + b_r, kk + b_c));
                bf[2 * fp][0] = t4[0]; bf[2 * fp][1] = t4[1];
                bf[2 * fp + 1][0] = t4[2]; bf[2 * fp + 1][1] = t4[3];
            }
#pragma unroll
            for (int fm = 0; fm < 4; fm++)
#pragma unroll
                for (int fn = 0; fn < 4; fn++) MMA16816(acc[fm][fn], af[fm], bf[fn]);
        }
    }

    // epilogue: e = exp(score) -> g_e (streamed) + deterministic partials
    const int stile4 = blockIdx.y * 4 + warp_n;
#pragma unroll
    for (int fm = 0; fm < 4; fm++) {
        int c = c0 + warp_m * 64 + fm * 16 + g;
        float r0 = 0.0f, r1 = 0.0f;
#pragma unroll
        for (int fn = 0; fn < 4; fn++) {
            int sc = s0 + warp_n * 32 + fn * 8 + 2 * tg;
            float e0 = fast_exp(acc[fm][fn][0]);
            float e1 = fast_exp(acc[fm][fn][1]);
            float e2 = fast_exp(acc[fm][fn][2]);
            float e3 = fast_exp(acc[fm][fn][3]);
            __stcs((__half2*)&g_e[((size_t)b * CP + c    ) * SS + sc], __floats2half2_rn(e0, e1));
            __stcs((__half2*)&g_e[((size_t)b * CP + c + 8) * SS + sc], __floats2half2_rn(e2, e3));
            r0 += e0 + e1;
            r1 += e2 + e3;
        }
        r0 += __shfl_xor_sync(0xffffffffu, r0, 1);
        r0 += __shfl_xor_sync(0xffffffffu, r0, 2);
        r1 += __shfl_xor_sync(0xffffffffu, r1, 1);
        r1 += __shfl_xor_sync(0xffffffffu, r1, 2);
        if (tg == 0) {
            g_Zp[(size_t)(b * CP + c    ) * 128 + stile4] = r0;
            g_Zp[(size_t)(b * CP + c + 8) * 128 + stile4] = r1;
        }
    }
#undef S1
}

// ---------------- K1b: deterministic final row sums --------------------------
__global__ __launch_bounds__(256) void k_rowsum() {
    int gw = (blockIdx.x * 256 + threadIdx.x) >> 5;
    if (gw >= BB * CP) return;
    int lane = threadIdx.x & 31;
    float4 v = *(const float4*)(g_Zp + (size_t)gw * 128 + lane * 4);
    float s = v.x + v.y + v.z + v.w;
#pragma unroll
    for (int o = 16; o; o >>= 1) s += __shfl_xor_sync(0xffffffffu, s, o);
    if (lane == 0) g_Z[gw] = s;
}

// ---------------- K2: logits GEMM + normalized attention write ---------------
// CTA 64(c) x 256(d), 256 threads. K=S=4096 in 64 chunks of 64 halves,
// 2-stage double buffer. Stage: rows 0..63 = A (e), rows 64..319 = B (xT).
// Attn write after the MMA loop (per-thread slot readback).
__global__ __launch_bounds__(256) void k_attnout(float* __restrict__ out_logits,
                                                 float* __restrict__ out_attn) {
    extern __shared__ __half sm2[];
#define S2(st_, r_, c_) sm2[(((st_) * 320) + (r_)) * P72 + (c_)]

    const int tid = threadIdx.x;
    const int wid = tid >> 5, lane = tid & 31;
    const int g = lane >> 2, tg = lane & 3;
    const int warp_m = wid >> 2, warp_n = wid & 3;

    const int c0 = blockIdx.x * 64;
    const int b  = blockIdx.y;

    float acc[2][8][4];
#pragma unroll
    for (int i = 0; i < 2; i++)
#pragma unroll
        for (int j = 0; j < 8; j++)
#pragma unroll
            for (int k = 0; k < 4; k++) acc[i][j][k] = 0.0f;

    const int lr = tid >> 3, c16 = tid & 7;   // loader row 0..31, 16B col 0..7

    // A (e): rows lr, lr+32 ; B (xT): rows lr+32i, i<8
    const __half* Ab = g_e + ((size_t)(b * CP + c0)) * SS;
    const __half* Bb = g_xT + ((size_t)b * DD) * SS;

    float iz[2];
    bool rok[2];
#pragma unroll
    for (int j = 0; j < 2; j++) {
        int r = lr + 32 * j;
        iz[j] = 1.0f / g_Z[b * CP + c0 + r];
        rok[j] = (c0 + r) < CC;
    }

    const int a_r = lane & 15, a_c = (lane >> 4) << 3;
    const int b_r = ((lane >> 4) << 3) + (lane & 7);
    const int b_c = ((lane >> 3) & 1) << 3;

    // prologue: stage 0 (kc = 0)
#pragma unroll
    for (int j = 0; j < 2; j++) {
        int r = lr + 32 * j;
        cpa16(&S2(0, r, c16 * 8), Ab + (size_t)r * SS + c16 * 8);
    }
#pragma unroll
    for (int i = 0; i < 8; i++) {
        int r = lr + 32 * i;
        cpa16(&S2(0, 64 + r, c16 * 8), Bb + (size_t)r * SS + c16 * 8);
    }
    CP_COMMIT();

#pragma unroll 1
    for (int ch = 0; ch < SS / KC; ch++) {
        const int buf = ch & 1;
        const int kc = ch * KC;
        CP_WAIT0();
        __syncthreads();
        if (ch + 1 < SS / KC) {
            const int nb = buf ^ 1;
            const int nkc = kc + KC;
#pragma unroll
            for (int j = 0; j < 2; j++) {
                int r = lr + 32 * j;
                cpa16(&S2(nb, r, c16 * 8), Ab + (size_t)r * SS + nkc + c16 * 8);
            }
#pragma unroll
            for (int i = 0; i < 8; i++) {
                int r = lr + 32 * i;
                cpa16(&S2(nb, 64 + r, c16 * 8), Bb + (size_t)r * SS + nkc + c16 * 8);
            }
            CP_COMMIT();
        }
#pragma unroll
        for (int kk = 0; kk < KC; kk += 16) {
            uint32_t af[2][4], bf[8][2];
#pragma unroll
            for (int fm = 0; fm < 2; fm++)
                ldsm4(af[fm], &S2(buf, warp_m * 32 + fm * 16 + a_r, kk + a_c));
#pragma unroll
            for (int fp = 0; fp < 4; fp++) {
                uint32_t t4[4];
                ldsm4(t4, &S2(buf, 64 + warp_n * 64 + fp * 16 + b_r, kk + b_c));
                bf[2 * fp][0] = t4[0]; bf[2 * fp][1] = t4[1];
                bf[2 * fp + 1][0] = t4[2]; bf[2 * fp + 1][1] = t4[3];
            }
#pragma unroll
            for (int fm = 0; fm < 2; fm++)
#pragma unroll
                for (int fn = 0; fn < 8; fn++) MMA16816(acc[fm][fn], af[fm], bf[fn]);
        }

        // normalized attention write (after MMAs; reads this thread's own slots)
#pragma unroll
        for (int j = 0; j < 2; j++) {
            if (!rok[j]) continue;
            int r = lr + 32 * j;
            int4 e4 = *(const int4*)&S2(buf, r, c16 * 8);
            const __half2* hp = (const __half2*)&e4;
            float2 f0 = __half22float2(hp[0]), f1 = __half22float2(hp[1]);
            float2 f2 = __half22float2(hp[2]), f3 = __half22float2(hp[3]);
            float4 o0 = {f0.x * iz[j], f0.y * iz[j], f1.x * iz[j], f1.y * iz[j]};
            float4 o1 = {f2.x * iz[j], f2.y * iz[j], f3.x * iz[j], f3.y * iz[j]};
            float* ap = out_attn + ((size_t)(b * CC + c0 + r)) * SS + kc + c16 * 8;
            __stwt((float4*)ap, o0);
            __stwt((float4*)(ap + 4), o1);
        }
    }

    // epilogue: logits = acc / Z (streamed)
#pragma unroll
    for (int fm = 0; fm < 2; fm++) {
        int c = c0 + warp_m * 32 + fm * 16 + g;
        float iz0 = 1.0f / __ldg(&g_Z[b * CP + c]);
        float iz1 = 1.0f / __ldg(&g_Z[b * CP + c + 8]);
#pragma unroll
        for (int fn = 0; fn < 8; fn++) {
            int d = warp_n * 64 + fn * 8 + 2 * tg;
            if (c < CC) {
                float2 v; v.x = acc[fm][fn][0] * iz0; v.y = acc[fm][fn][1] * iz0;
                __stwt((float2*)(out_logits + ((size_t)(b * CC + c)) * DD + d), v);
            }
            if (c + 8 < CC) {
                float2 v; v.x = acc[fm][fn][2] * iz1; v.y = acc[fm][fn][3] * iz1;
                __stwt((float2*)(out_logits + ((size_t)(b * CC + c + 8)) * DD + d), v);
            }
        }
    }
#undef S2
}

// ---------------- launch -----------------------------------------------------
extern "C" void kernel_launch(void* const* d_in, const int* in_sizes, int n_in,
                              void* d_out, int out_size) {
    const float* x = (const float*)d_in[0];
    const float* W = (const float*)d_in[1];
    float* logits = (float*)d_out;                        // [B, C, D]
    float* attn   = (float*)d_out + (size_t)BB * CC * DD; // [B, C, S]

    const int k1_smem = 2 * 256 * P72 * (int)sizeof(__half);  // 73728
    const int k2_smem = 2 * 320 * P72 * (int)sizeof(__half);  // 92160
    cudaFuncSetAttribute(k_scores,  cudaFuncAttributeMaxDynamicSharedMemorySize, k1_smem);
    cudaFuncSetAttribute(k_attnout, cudaFuncAttributeMaxDynamicSharedMemorySize, k2_smem);

    k_conv<<<dim3(DD / 128, SS / 32, BB + 1), 256>>>(x, W);
    k_scores<<<dim3(CP / 128, SS / 128, BB), 256, k1_smem>>>();
    k_rowsum<<<(BB * CP + 7) / 8, 256>>>();
    k_attnout<<<dim3(CP / 64, BB), 256, k2_smem>>>(logits, attn);
}

// round 17
// speedup vs baseline: 1.3664x; 1.3664x over previous
#include <cuda_runtime.h>
#include <cuda_fp16.h>
#include <cstdint>

// Problem dims
#define BB 4
#define SS 4096
#define DD 256
#define CC 8921
#define CP 8960   // C padded to multiple of 128
#define KC 32
#define PITCH 40  // halves; 80B rows -> LDSM conflict-free, 16B aligned

// ---------------- device scratch (zero-initialized at module load) ----------
__device__ __align__(256) __half g_xh[BB * SS * DD];            // x fp16 [b][s][d]
__device__ __align__(256) __half g_xT[BB * DD * SS];            // x^T fp16 [b][d][s]
__device__ __align__(256) __half g_Wh[CP * DD];                 // W fp16 (pad rows stay 0)
__device__ __align__(256) __half g_e [(size_t)BB * CP * SS];    // exp(scores) fp16
__device__ __align__(256) float  g_Zp[(size_t)BB * CP * 128];   // per-(row, stile*4+warp) partials

// ---------------- helpers ---------------------------------------------------
__device__ __forceinline__ float fast_exp(float x) {
    float y = x * 1.4426950408889634f;
    y = fminf(fmaxf(y, -80.0f), 80.0f);
    float n = rintf(y);
    float f = y - n;
    float p = 1.3333558146e-3f;
    p = fmaf(p, f, 9.6181291076e-3f);
    p = fmaf(p, f, 5.5504108664e-2f);
    p = fmaf(p, f, 2.4022650696e-1f);
    p = fmaf(p, f, 6.9314718056e-1f);
    p = fmaf(p, f, 1.0f);
    return p * __int_as_float((__float2int_rn(n) + 127) << 23);
}

#define MMA16816(d, a, b)                                                     \
    asm volatile(                                                             \
        "mma.sync.aligned.m16n8k16.row.col.f32.f16.f16.f32 "                  \
        "{%0,%1,%2,%3}, {%4,%5,%6,%7}, {%8,%9}, {%0,%1,%2,%3};\n"             \
        : "+f"((d)[0]), "+f"((d)[1]), "+f"((d)[2]), "+f"((d)[3])              \
        : "r"((a)[0]), "r"((a)[1]), "r"((a)[2]), "r"((a)[3]),                 \
          "r"((b)[0]), "r"((b)[1]))

__device__ __forceinline__ void ldsm4(uint32_t* r, const __half* p) {
    uint32_t a = (uint32_t)__cvta_generic_to_shared(p);
    asm volatile("ldmatrix.sync.aligned.m8n8.x4.shared.b16 {%0,%1,%2,%3}, [%4];\n"
                 : "=r"(r[0]), "=r"(r[1]), "=r"(r[2]), "=r"(r[3]) : "r"(a));
}

__device__ __forceinline__ void cpa16(const __half* smem_dst, const __half* gmem_src) {
    uint32_t d = (uint32_t)__cvta_generic_to_shared(smem_dst);
    asm volatile("cp.async.cg.shared.global [%0], [%1], 16;\n" :: "r"(d), "l"(gmem_src));
}
#define CP_COMMIT() asm volatile("cp.async.commit_group;\n")
#define CP_WAIT2()  asm volatile("cp.async.wait_group 2;\n")

// ---------------- K0: fused conversions (x -> fp16 + x^T; W -> fp16) --------
__global__ __launch_bounds__(256) void k_conv(const float* __restrict__ x,
                                              const float* __restrict__ W) {
    const int tid = threadIdx.x;
    if (blockIdx.z == BB) {
        int bid = blockIdx.y * 2 + blockIdx.x;           // 0..255
        int i0 = bid * 256 + tid;
        const int n4 = CC * DD / 4;
        for (int i = i0; i < n4; i += 256 * 256) {
            float4 v = *(const float4*)(W + (size_t)i * 4);
            __half2 h0 = __floats2half2_rn(v.x, v.y);
            __half2 h1 = __floats2half2_rn(v.z, v.w);
            *(__half2*)(g_Wh + (size_t)i * 4)     = h0;
            *(__half2*)(g_Wh + (size_t)i * 4 + 2) = h1;
        }
        return;
    }
    __shared__ float t[32][132];
    const int d0 = blockIdx.x * 128, s0 = blockIdx.y * 32, b = blockIdx.z;
#pragma unroll
    for (int r = 0; r < 4; r++) {
        int slot = r * 256 + tid;
        int s = slot >> 5;
        int d = (slot & 31) * 4;
        float4 v = *(const float4*)(x + ((size_t)b * SS + s0 + s) * DD + d0 + d);
        __half2 h0 = __floats2half2_rn(v.x, v.y);
        __half2 h1 = __floats2half2_rn(v.z, v.w);
        *(__half2*)(g_xh + ((size_t)b * SS + s0 + s) * DD + d0 + d)     = h0;
        *(__half2*)(g_xh + ((size_t)b * SS + s0 + s) * DD + d0 + d + 2) = h1;
        *(float4*)&t[s][d] = v;
    }
    __syncthreads();
#pragma unroll
    for (int r = 0; r < 8; r++) {
        int slot = r * 256 + tid;
        int d = slot >> 4;
        int sp = slot & 15;
        __half2 h = __floats2half2_rn(t[2 * sp][d], t[2 * sp + 1][d]);
        *(__half2*)(g_xT + ((size_t)b * DD + d0 + d) * SS + s0 + 2 * sp) = h;
    }
}

// ---------------- K1: scores GEMM + exp + deterministic partial row sums ----
// CTA 128(c) x 128(s), 256 threads, K=D=256 in 8 chunks of 32,
// 4-stage cp.async ring (wait_group 2). R8-identical.
__global__ __launch_bounds__(256) void k_scores() {
    extern __shared__ __half sm1[];
    __half* Asb = sm1;                          // [4][128][PITCH]
    __half* Bsb = sm1 + 4 * 128 * PITCH;        // [4][128][PITCH]
#define A1(st_, r_, c_) Asb[(((st_) * 128) + (r_)) * PITCH + (c_)]
#define B1(st_, r_, c_) Bsb[(((st_) * 128) + (r_)) * PITCH + (c_)]

    const int tid = threadIdx.x;
    const int wid = tid >> 5, lane = tid & 31;
    const int g = lane >> 2, tg = lane & 3;
    const int warp_m = wid >> 2, warp_n = wid & 3;

    const int c0 = blockIdx.x * 128;
    const int s0 = blockIdx.y * 128;
    const int b  = blockIdx.z;

    const __half* Wt = g_Wh + (size_t)c0 * DD;
    const __half* Xt = g_xh + ((size_t)b * SS + s0) * DD;

    float acc[4][4][4];
#pragma unroll
    for (int i = 0; i < 4; i++)
#pragma unroll
        for (int j = 0; j < 4; j++)
#pragma unroll
            for (int k = 0; k < 4; k++) acc[i][j][k] = 0.0f;

    const int rA = tid >> 2, cA = (tid & 3) * 8;  // rows rA, rA+64

    const int a_r = lane & 15, a_c = (lane >> 4) << 3;
    const int b_r = ((lane >> 4) << 3) + (lane & 7);
    const int b_c = ((lane >> 3) & 1) << 3;

    // prologue: stages 0..2
#pragma unroll
    for (int st = 0; st < 3; st++) {
        int kc = st * KC;
        cpa16(&A1(st, rA,      cA), Wt + (size_t)rA * DD + kc + cA);
        cpa16(&A1(st, rA + 64, cA), Wt + (size_t)(rA + 64) * DD + kc + cA);
        cpa16(&B1(st, rA,      cA), Xt + (size_t)rA * DD + kc + cA);
        cpa16(&B1(st, rA + 64, cA), Xt + (size_t)(rA + 64) * DD + kc + cA);
        CP_COMMIT();
    }

#pragma unroll 1
    for (int st = 0; st < DD / KC; st++) {
        const int buf = st & 3;
        CP_WAIT2();
        __syncthreads();
        if (st + 3 < DD / KC) {
            const int ns = (st + 3) & 3;
            const int kc = (st + 3) * KC;
            cpa16(&A1(ns, rA,      cA), Wt + (size_t)rA * DD + kc + cA);
            cpa16(&A1(ns, rA + 64, cA), Wt + (size_t)(rA + 64) * DD + kc + cA);
            cpa16(&B1(ns, rA,      cA), Xt + (size_t)rA * DD + kc + cA);
            cpa16(&B1(ns, rA + 64, cA), Xt + (size_t)(rA + 64) * DD + kc + cA);
        }
        CP_COMMIT();
#pragma unroll
        for (int kk = 0; kk < KC; kk += 16) {
            uint32_t af[4][4], bf[4][2];
#pragma unroll
            for (int fm = 0; fm < 4; fm++)
                ldsm4(af[fm], &A1(buf, warp_m * 64 + fm * 16 + a_r, kk + a_c));
#pragma unroll
            for (int fp = 0; fp < 2; fp++) {
                uint32_t t4[4];
                ldsm4(t4, &B1(buf, warp_n * 32 + fp * 16 + b_r, kk + b_c));
                bf[2 * fp][0] = t4[0]; bf[2 * fp][1] = t4[1];
                bf[2 * fp + 1][0] = t4[2]; bf[2 * fp + 1][1] = t4[3];
            }
#pragma unroll
            for (int fm = 0; fm < 4; fm++)
#pragma unroll
                for (int fn = 0; fn < 4; fn++) MMA16816(acc[fm][fn], af[fm], bf[fn]);
        }
    }

    // epilogue: e = exp(score) -> g_e (streamed), plus deterministic partials
    const int stile4 = blockIdx.y * 4 + warp_n;
#pragma unroll
    for (int fm = 0; fm < 4; fm++) {
        int c = c0 + warp_m * 64 + fm * 16 + g;
        float r0 = 0.0f, r1 = 0.0f;
#pragma unroll
        for (int fn = 0; fn < 4; fn++) {
            int sc = s0 + warp_n * 32 + fn * 8 + 2 * tg;
            float e0 = fast_exp(acc[fm][fn][0]);
            float e1 = fast_exp(acc[fm][fn][1]);
            float e2 = fast_exp(acc[fm][fn][2]);
            float e3 = fast_exp(acc[fm][fn][3]);
            __stcs((__half2*)&g_e[((size_t)b * CP + c    ) * SS + sc], __floats2half2_rn(e0, e1));
            __stcs((__half2*)&g_e[((size_t)b * CP + c + 8) * SS + sc], __floats2half2_rn(e2, e3));
            r0 += e0 + e1;
            r1 += e2 + e3;
        }
        r0 += __shfl_xor_sync(0xffffffffu, r0, 1);
        r0 += __shfl_xor_sync(0xffffffffu, r0, 2);
        r1 += __shfl_xor_sync(0xffffffffu, r1, 1);
        r1 += __shfl_xor_sync(0xffffffffu, r1, 2);
        if (tg == 0) {
            g_Zp[(size_t)(b * CP + c    ) * 128 + stile4] = r0;
            g_Zp[(size_t)(b * CP + c + 8) * 128 + stile4] = r1;
        }
    }
#undef A1
#undef B1
}

// ---------------- K2: logits GEMM + normalized attention write ---------------
// CTA 64(c) x 256(d), 256 threads, K=S=4096 in 128 chunks of 32,
// 4-stage cp.async ring (R8 mainloop). New: per-CTA Z reduction in the
// prologue (replaces k_rowsum), attn write after the MMA loop.
__global__ __launch_bounds__(256) void k_attnout(float* __restrict__ out_logits,
                                                 float* __restrict__ out_attn) {
    extern __shared__ __half sm2[];
    __half* Asb = sm2;                         // [4][64][PITCH]
    __half* Bsb = sm2 + 4 * 64 * PITCH;        // [4][256][PITCH]
    float*  Zs  = (float*)(sm2 + 4 * (64 + 256) * PITCH);   // [64]
#define A2(st_, r_, c_) Asb[(((st_) * 64)  + (r_)) * PITCH + (c_)]
#define B2(st_, r_, c_) Bsb[(((st_) * 256) + (r_)) * PITCH + (c_)]

    const int tid = threadIdx.x;
    const int wid = tid >> 5, lane = tid & 31;
    const int g = lane >> 2, tg = lane & 3;
    const int warp_m = wid >> 2, warp_n = wid & 3;

    const int c0 = blockIdx.x * 64;
    const int b  = blockIdx.y;

    float acc[2][8][4];
#pragma unroll
    for (int i = 0; i < 2; i++)
#pragma unroll
        for (int j = 0; j < 8; j++)
#pragma unroll
            for (int k = 0; k < 4; k++) acc[i][j][k] = 0.0f;

    const int arow = tid >> 2, acol = (tid & 3) * 8;
    const __half* Ab = g_e + ((size_t)(b * CP + c0 + arow)) * SS + acol;
    const bool arow_ok = (c0 + arow) < CC;
    float* attn_base = out_attn + ((size_t)(b * CC + c0 + arow)) * SS + acol;

    const int brow = tid >> 2, bcol = (tid & 3) * 8;
    const __half* Bb = g_xT + ((size_t)b * DD + brow) * SS + bcol;

    const int a_r = lane & 15, a_c = (lane >> 4) << 3;
    const int b_r = ((lane >> 4) << 3) + (lane & 7);
    const int b_c = ((lane >> 3) & 1) << 3;

    // prologue: stages 0..2 (fire loads first so Z reduction overlaps them)
#pragma unroll
    for (int st = 0; st < 3; st++) {
        int kc = st * KC;
        cpa16(&A2(st, arow, acol), Ab + kc);
#pragma unroll
        for (int i = 0; i < 4; i++)
            cpa16(&B2(st, brow + i * 64, bcol), Bb + (size_t)(i * 64) * SS + kc);
        CP_COMMIT();
    }

    // Z reduction for this CTA's 64 c-rows (deterministic fixed order).
    // thread t: row = t>>2, quarter = t&3 (32 partials each), then 2 shuffles.
    {
        const int zr = tid >> 2, zq = tid & 3;
        const float* zp = g_Zp + (size_t)(b * CP + c0 + zr) * 128 + zq * 32;
        float s = 0.0f;
#pragma unroll
        for (int i = 0; i < 8; i++) {
            float4 v = *(const float4*)(zp + i * 4);
            s += v.x + v.y + v.z + v.w;
        }
        s += __shfl_xor_sync(0xffffffffu, s, 1);
        s += __shfl_xor_sync(0xffffffffu, s, 2);
        if (zq == 0) Zs[zr] = s;
    }
    __syncthreads();
    const float invZa = 1.0f / Zs[arow];

#pragma unroll 1
    for (int st = 0; st < SS / KC; st++) {
        const int buf = st & 3;
        CP_WAIT2();
        __syncthreads();
        if (st + 3 < SS / KC) {
            const int ns = (st + 3) & 3;
            const int kc = (st + 3) * KC;
            cpa16(&A2(ns, arow, acol), Ab + kc);
#pragma unroll
            for (int i = 0; i < 4; i++)
                cpa16(&B2(ns, brow + i * 64, bcol), Bb + (size_t)(i * 64) * SS + kc);
        }
        CP_COMMIT();

#pragma unroll
        for (int kk = 0; kk < KC; kk += 16) {
            uint32_t af[2][4], bf[8][2];
#pragma unroll
            for (int fm = 0; fm < 2; fm++)
                ldsm4(af[fm], &A2(buf, warp_m * 32 + fm * 16 + a_r, kk + a_c));
#pragma unroll
            for (int fp = 0; fp < 4; fp++) {
                uint32_t t4[4];
                ldsm4(t4, &B2(buf, warp_n * 64 + fp * 16 + b_r, kk + b_c));
                bf[2 * fp][0] = t4[0]; bf[2 * fp][1] = t4[1];
                bf[2 * fp + 1][0] = t4[2]; bf[2 * fp + 1][1] = t4[3];
            }
#pragma unroll
            for (int fm = 0; fm < 2; fm++)
#pragma unroll
                for (int fn = 0; fn < 8; fn++) MMA16816(acc[fm][fn], af[fm], bf[fn]);
        }

        // normalized attention write (after MMAs; reads this thread's own slot;
        // slot is next overwritten by this thread's own cpa16 at iter st+1)
        if (arow_ok) {
            int4 e4 = *(const int4*)&A2(buf, arow, acol);
            const __half2* hp = (const __half2*)&e4;
            float2 f0 = __half22float2(hp[0]), f1 = __half22float2(hp[1]);
            float2 f2 = __half22float2(hp[2]), f3 = __half22float2(hp[3]);
            float4 o0 = {f0.x * invZa, f0.y * invZa, f1.x * invZa, f1.y * invZa};
            float4 o1 = {f2.x * invZa, f2.y * invZa, f3.x * invZa, f3.y * invZa};
            float* ap = attn_base + st * KC;
            __stwt((float4*)ap, o0);
            __stwt((float4*)(ap + 4), o1);
        }
    }

    // epilogue: logits = acc / Z (streamed)
#pragma unroll
    for (int fm = 0; fm < 2; fm++) {
        int c = c0 + warp_m * 32 + fm * 16 + g;
        float iz0 = 1.0f / Zs[c - c0];
        float iz1 = 1.0f / Zs[c - c0 + 8];
#pragma unroll
        for (int fn = 0; fn < 8; fn++) {
            int d = warp_n * 64 + fn * 8 + 2 * tg;
            if (c < CC) {
                float2 v; v.x = acc[fm][fn][0] * iz0; v.y = acc[fm][fn][1] * iz0;
                __stwt((float2*)(out_logits + ((size_t)(b * CC + c)) * DD + d), v);
            }
            if (c + 8 < CC) {
                float2 v; v.x = acc[fm][fn][2] * iz1; v.y = acc[fm][fn][3] * iz1;
                __stwt((float2*)(out_logits + ((size_t)(b * CC + c + 8)) * DD + d), v);
            }
        }
    }
#undef A2
#undef B2
}

// ---------------- launch -----------------------------------------------------
extern "C" void kernel_launch(void* const* d_in, const int* in_sizes, int n_in,
                              void* d_out, int out_size) {
    const float* x = (const float*)d_in[0];
    const float* W = (const float*)d_in[1];
    float* logits = (float*)d_out;                        // [B, C, D]
    float* attn   = (float*)d_out + (size_t)BB * CC * DD; // [B, C, S]

    const int k1_smem = 4 * (128 + 128) * PITCH * (int)sizeof(__half);        // 81920
    const int k2_smem = 4 * (64 + 256) * PITCH * (int)sizeof(__half) + 256;   // 102656
    cudaFuncSetAttribute(k_scores,  cudaFuncAttributeMaxDynamicSharedMemorySize, k1_smem);
    cudaFuncSetAttribute(k_attnout, cudaFuncAttributeMaxDynamicSharedMemorySize, k2_smem);

    k_conv<<<dim3(DD / 128, SS / 32, BB + 1), 256>>>(x, W);
    k_scores<<<dim3(CP / 128, SS / 128, BB), 256, k1_smem>>>();
    k_attnout<<<dim3(CP / 64, BB), 256, k2_smem>>>(logits, attn);
}